// round 1
// baseline (speedup 1.0000x reference)
#include <cuda_runtime.h>
#include <math.h>

#define IH 512
#define IW 512
#define NB 32
#define TILE 32

// Composed / helper weights, filled by prep kernel each launch (weights are inputs).
__device__ float d_Gx5[25];   // gauss∘sobel_x composed 5x5
__device__ float d_Gy5[25];   // gauss∘sobel_y composed 5x5
__device__ float d_T5[25];    // dir∘nms composed 5x5 (summed over 8 dirs)
__device__ float d_NM[81];    // NM[v][s] = sum_k nms_k[v]*dir_k[s]  (border path)
__device__ float d_G3[9], d_SX[9], d_SY[9];

__global__ void prep_weights(const float* __restrict__ gauss,
                             const float* __restrict__ sx,
                             const float* __restrict__ sy,
                             const float* __restrict__ dirw,
                             const float* __restrict__ nmsw) {
    int t = threadIdx.x;
    if (t < 9) { d_G3[t] = gauss[t]; d_SX[t] = sx[t]; d_SY[t] = sy[t]; }
    if (t < 25) {
        int wy = t / 5 - 2, wx = t % 5 - 2;
        float ax = 0.f, ay = 0.f, tc = 0.f;
        for (int uy = -1; uy <= 1; ++uy)
            for (int ux = -1; ux <= 1; ++ux) {
                int vy = wy - uy, vx = wx - ux;
                if (vy < -1 || vy > 1 || vx < -1 || vx > 1) continue;
                int ui = (uy + 1) * 3 + (ux + 1);
                int vi = (vy + 1) * 3 + (vx + 1);
                float g = gauss[ui];
                ax += g * sx[vi];
                ay += g * sy[vi];
                for (int k = 0; k < 8; ++k)
                    tc += dirw[k * 9 + ui] * nmsw[k * 9 + vi];
            }
        d_Gx5[t] = ax; d_Gy5[t] = ay; d_T5[t] = tc;
    }
    if (t < 81) {
        int v = t / 9, s = t % 9;
        float acc = 0.f;
        for (int k = 0; k < 8; ++k) acc += nmsw[k * 9 + v] * dirw[k * 9 + s];
        d_NM[t] = acc;
    }
}

__global__ __launch_bounds__(256) void canny_fused(const float* __restrict__ img,
                                                   float* __restrict__ out) {
    __shared__ float s_mean[40][41];   // mean tile, halo 4, origin (ty0-4, tx0-4)
    __shared__ float s_mag[36][37];    // mag tile,  halo 2, origin (ty0-2, tx0-2)
    __shared__ float wGx[25], wGy[25], wT[25], wNM[81], wG[9], wSX[9], wSY[9];

    const int tid = threadIdx.y * 32 + threadIdx.x;
    if (tid < 25) { wGx[tid] = d_Gx5[tid]; wGy[tid] = d_Gy5[tid]; wT[tid] = d_T5[tid]; }
    if (tid < 81) wNM[tid] = d_NM[tid];
    if (tid < 9)  { wG[tid] = d_G3[tid]; wSX[tid] = d_SX[tid]; wSY[tid] = d_SY[tid]; }

    const int b   = blockIdx.z;
    const int ty0 = blockIdx.y * TILE;
    const int tx0 = blockIdx.x * TILE;
    const float* img0 = img + (size_t)b * 3 * IH * IW;

    // ---- Phase 1: channel-mean tile (zero outside image domain) ----
    for (int idx = tid; idx < 40 * 40; idx += 256) {
        int ly = idx / 40, lx = idx % 40;
        int gy = ty0 - 4 + ly, gx = tx0 - 4 + lx;
        float v = 0.f;
        if (gy >= 0 && gy < IH && gx >= 0 && gx < IW) {
            int off = gy * IW + gx;
            v = (img0[off] + img0[IH * IW + off] + img0[2 * IH * IW + off]) * (1.0f / 3.0f);
        }
        s_mean[ly][lx] = v;
    }
    __syncthreads();

    // ---- Phase 2: gradient magnitude on 36x36 (zero outside domain) ----
    for (int idx = tid; idx < 36 * 36; idx += 256) {
        int ly = idx / 36, lx = idx % 36;
        int gy = ty0 - 2 + ly, gx = tx0 - 2 + lx;
        float m = 0.f;
        if (gy >= 0 && gy < IH && gx >= 0 && gx < IW) {
            float gxv = 0.f, gyv = 0.f;
            if (gy >= 1 && gy <= IH - 2 && gx >= 1 && gx <= IW - 2) {
                // interior: composed 5x5 (intermediate blur positions all in-domain)
#pragma unroll
                for (int wy = 0; wy < 5; ++wy)
#pragma unroll
                    for (int wx = 0; wx < 5; ++wx) {
                        float mv = s_mean[ly + wy][lx + wx];
                        gxv = fmaf(wGx[wy * 5 + wx], mv, gxv);
                        gyv = fmaf(wGy[wy * 5 + wx], mv, gyv);
                    }
            } else {
                // border ring: exact two-stage with zero-padded intermediate
#pragma unroll
                for (int uy = 0; uy < 3; ++uy)
#pragma unroll
                    for (int ux = 0; ux < 3; ++ux) {
                        int ry = gy + uy - 1, rx = gx + ux - 1;
                        if (ry < 0 || ry >= IH || rx < 0 || rx >= IW) continue;
                        float bl = 0.f;
#pragma unroll
                        for (int vy = 0; vy < 3; ++vy)
#pragma unroll
                            for (int vx = 0; vx < 3; ++vx)
                                bl = fmaf(wG[vy * 3 + vx],
                                          s_mean[ly + uy + vy][lx + ux + vx], bl);
                        gxv = fmaf(wSX[uy * 3 + ux], bl, gxv);
                        gyv = fmaf(wSY[uy * 3 + ux], bl, gyv);
                    }
            }
            m = sqrtf(gxv * gxv + gyv * gyv);
        }
        s_mag[ly][lx] = m;
    }
    __syncthreads();

    // ---- Phase 3: thin edges on 32x32 output tile ----
    float* outb = out + (size_t)b * IH * IW;
#pragma unroll
    for (int r = 0; r < 4; ++r) {
        int row = threadIdx.y + r * 8;
        int gy = ty0 + row, gx = tx0 + threadIdx.x;
        float acc = 0.f;
        if (gy >= 1 && gy <= IH - 2 && gx >= 1 && gx <= IW - 2) {
            // interior: composed 5x5 over mag
#pragma unroll
            for (int wy = 0; wy < 5; ++wy)
#pragma unroll
                for (int wx = 0; wx < 5; ++wx)
                    acc = fmaf(wT[wy * 5 + wx],
                               s_mag[row + wy][threadIdx.x + wx], acc);
        } else {
            // border ring: exact two-stage (dir conv zero-padded, then nms)
#pragma unroll
            for (int vy = 0; vy < 3; ++vy)
#pragma unroll
                for (int vx = 0; vx < 3; ++vx) {
                    int ry = gy + vy - 1, rx = gx + vx - 1;
                    if (ry < 0 || ry >= IH || rx < 0 || rx >= IW) continue;
#pragma unroll
                    for (int sy = 0; sy < 3; ++sy)
#pragma unroll
                        for (int sx2 = 0; sx2 < 3; ++sx2)
                            acc = fmaf(wNM[(vy * 3 + vx) * 9 + sy * 3 + sx2],
                                       s_mag[row + vy + sy][threadIdx.x + vx + sx2], acc);
                }
        }
        outb[gy * IW + gx] = acc;
    }
}

extern "C" void kernel_launch(void* const* d_in, const int* in_sizes, int n_in,
                              void* d_out, int out_size) {
    const float* img   = (const float*)d_in[0];
    const float* gauss = (const float*)d_in[1];
    const float* sx    = (const float*)d_in[2];
    const float* sy    = (const float*)d_in[3];
    const float* dirw  = (const float*)d_in[4];
    const float* nmsw  = (const float*)d_in[5];
    float* out = (float*)d_out;

    prep_weights<<<1, 128>>>(gauss, sx, sy, dirw, nmsw);

    dim3 grid(IW / TILE, IH / TILE, NB);
    dim3 block(32, 8);
    canny_fused<<<grid, block>>>(img, out);
}

// round 3
// speedup vs baseline: 2.4437x; 2.4437x over previous
#include <cuda_runtime.h>
#include <math.h>

#define IH 512
#define IW 512
#define NB 32
#define TX 64
#define TY 32
// mean tile: 72x40 (halo 4), row stride padded to 76 (mult of 4)
#define MEAN_H 40
#define MEAN_S 76
// mag tile: 68x36 (halo 2), row stride padded to 72
#define MAG_H 36
#define MAG_S 72

typedef unsigned long long u64;

// weights prepared per launch (they are runtime inputs)
__device__ float d_G3[9], d_SX[9], d_SY[9];
__device__ float d_T5[25];     // dir∘nms composed 5x5
__device__ float d_NM[81];     // border helper: NM[v][s] = sum_k nms_k[v]*dir_k[s]
__device__ u64   d_Pxy[25];    // packed (Gx5[i], Gy5[i])

__device__ __forceinline__ u64 pack2(float lo, float hi) {
    u64 d; asm("mov.b64 %0, {%1,%2};" : "=l"(d) : "f"(lo), "f"(hi)); return d;
}
__device__ __forceinline__ void unpack2(u64 v, float& lo, float& hi) {
    asm("mov.b64 {%0,%1}, %2;" : "=f"(lo), "=f"(hi) : "l"(v));
}
__device__ __forceinline__ u64 fma2(u64 a, u64 b, u64 c) {
    u64 d; asm("fma.rn.f32x2 %0, %1, %2, %3;" : "=l"(d) : "l"(a), "l"(b), "l"(c)); return d;
}

__global__ void prep_weights(const float* __restrict__ g,
                             const float* __restrict__ sx,
                             const float* __restrict__ sy,
                             const float* __restrict__ dirw,
                             const float* __restrict__ nmsw) {
    int t = threadIdx.x;
    if (t < 9) { d_G3[t] = g[t]; d_SX[t] = sx[t]; d_SY[t] = sy[t]; }
    if (t < 25) {
        int wy = t / 5 - 2, wx = t % 5 - 2;
        float ax = 0.f, ay = 0.f, tc = 0.f;
        for (int uy = -1; uy <= 1; ++uy)
            for (int ux = -1; ux <= 1; ++ux) {
                int vy = wy - uy, vx = wx - ux;
                if (vy < -1 || vy > 1 || vx < -1 || vx > 1) continue;
                int ui = (uy + 1) * 3 + (ux + 1);
                int vi = (vy + 1) * 3 + (vx + 1);
                ax += g[ui] * sx[vi];
                ay += g[ui] * sy[vi];
                for (int k = 0; k < 8; ++k)
                    tc += dirw[k * 9 + ui] * nmsw[k * 9 + vi];
            }
        d_Pxy[t] = pack2(ax, ay);
        d_T5[t] = tc;
    }
    if (t < 81) {
        int v = t / 9, s = t % 9;
        float a = 0.f;
        for (int k = 0; k < 8; ++k) a += nmsw[k * 9 + v] * dirw[k * 9 + s];
        d_NM[t] = a;
    }
}

__global__ __launch_bounds__(256) void canny_fused(const float* __restrict__ img,
                                                   float* __restrict__ out) {
    __shared__ __align__(16) float s_mean[MEAN_H][MEAN_S];
    __shared__ __align__(16) float s_mag[MAG_H][MAG_S];
    __shared__ u64 sPxy[25];
    __shared__ float sT5[25], sNM[81], sG[9], sSX[9], sSY[9];

    const int tid = threadIdx.x;
    if (tid < 25) { sPxy[tid] = d_Pxy[tid]; sT5[tid] = d_T5[tid]; }
    if (tid < 81) sNM[tid] = d_NM[tid];
    if (tid < 9)  { sG[tid] = d_G3[tid]; sSX[tid] = d_SX[tid]; sSY[tid] = d_SY[tid]; }

    const int b   = blockIdx.z;
    const int ty0 = blockIdx.y * TY;
    const int tx0 = blockIdx.x * TX;
    const float* im = img + (size_t)b * 3 * IH * IW;
    const bool edge = (blockIdx.x == 0) | (blockIdx.x == gridDim.x - 1) |
                      (blockIdx.y == 0) | (blockIdx.y == gridDim.y - 1);

    // ---- Phase 1: channel-mean tile, float4 groups (18 groups x 40 rows) ----
    for (int t = tid; t < 18 * MEAN_H; t += 256) {
        int r = t / 18, xg = t % 18;
        int gy = ty0 - 4 + r, gx = tx0 - 4 + 4 * xg;
        float4 v;
        if (!edge || (gy >= 0 && gy < IH && gx >= 0 && gx + 3 < IW)) {
            const float* p = im + gy * IW + gx;
            float4 a  = *(const float4*)p;
            float4 c1 = *(const float4*)(p + IH * IW);
            float4 c2 = *(const float4*)(p + 2 * IH * IW);
            v.x = (a.x + c1.x + c2.x) * (1.0f / 3.0f);
            v.y = (a.y + c1.y + c2.y) * (1.0f / 3.0f);
            v.z = (a.z + c1.z + c2.z) * (1.0f / 3.0f);
            v.w = (a.w + c1.w + c2.w) * (1.0f / 3.0f);
        } else {
            float tmp[4];
#pragma unroll
            for (int j = 0; j < 4; ++j) {
                int gxx = gx + j;
                float val = 0.f;
                if (gy >= 0 && gy < IH && gxx >= 0 && gxx < IW) {
                    int off = gy * IW + gxx;
                    val = (im[off] + im[IH * IW + off] + im[2 * IH * IW + off]) * (1.0f / 3.0f);
                }
                tmp[j] = val;
            }
            v = make_float4(tmp[0], tmp[1], tmp[2], tmp[3]);
        }
        *(float4*)&s_mean[r][4 * xg] = v;
    }
    __syncthreads();

    // ---- Phase 2: grad magnitude, 4-wide groups, packed (gx,gy) FFMA2 ----
    for (int t = tid; t < 17 * MAG_H; t += 256) {
        int ly = t / 17, xg = t % 17, i0 = 4 * xg;
        u64 acc[4] = {0ull, 0ull, 0ull, 0ull};
#pragma unroll
        for (int wy = 0; wy < 5; ++wy) {
            const float* rp = &s_mean[ly + wy][i0];
            float4 a = *(const float4*)rp;
            float4 bq = *(const float4*)(rp + 4);
            u64 v[8];
            v[0] = pack2(a.x, a.x);  v[1] = pack2(a.y, a.y);
            v[2] = pack2(a.z, a.z);  v[3] = pack2(a.w, a.w);
            v[4] = pack2(bq.x, bq.x); v[5] = pack2(bq.y, bq.y);
            v[6] = pack2(bq.z, bq.z); v[7] = pack2(bq.w, bq.w);
#pragma unroll
            for (int j = 0; j < 4; ++j)
#pragma unroll
                for (int k = 0; k < 5; ++k)
                    acc[j] = fma2(sPxy[wy * 5 + k], v[j + k], acc[j]);
        }
        float m[4];
#pragma unroll
        for (int j = 0; j < 4; ++j) {
            float gxv, gyv; unpack2(acc[j], gxv, gyv);
            m[j] = sqrtf(gxv * gxv + gyv * gyv);
        }
        if (edge) {
            int gy = ty0 - 2 + ly, gxb = tx0 - 2 + i0;
#pragma unroll
            for (int j = 0; j < 4; ++j) {
                int gxx = gxb + j;
                if (gy < 0 || gy >= IH || gxx < 0 || gxx >= IW) {
                    m[j] = 0.f;
                } else if (gy < 1 || gy > IH - 2 || gxx < 1 || gxx > IW - 2) {
                    float ax = 0.f, ay = 0.f;
                    for (int uy = 0; uy < 3; ++uy)
                        for (int ux = 0; ux < 3; ++ux) {
                            int ry = gy + uy - 1, rx = gxx + ux - 1;
                            if (ry < 0 || ry >= IH || rx < 0 || rx >= IW) continue;
                            float bl = 0.f;
                            for (int vy = 0; vy < 3; ++vy)
                                for (int vx = 0; vx < 3; ++vx)
                                    bl = fmaf(sG[vy * 3 + vx],
                                              s_mean[ly + uy + vy][i0 + j + ux + vx], bl);
                            ax = fmaf(sSX[uy * 3 + ux], bl, ax);
                            ay = fmaf(sSY[uy * 3 + ux], bl, ay);
                        }
                    m[j] = sqrtf(ax * ax + ay * ay);
                }
            }
        }
        *(float4*)&s_mag[ly][i0] = make_float4(m[0], m[1], m[2], m[3]);
    }
    __syncthreads();

    // ---- Phase 3: thin edges, 4-wide groups, scalar FFMA composed 5x5 ----
    float* ob = out + (size_t)b * IH * IW;
#pragma unroll
    for (int s = 0; s < 2; ++s) {
        int t = tid + s * 256;
        int row = t >> 4, xg = t & 15, c0 = 4 * xg;
        float o[4] = {0.f, 0.f, 0.f, 0.f};
#pragma unroll
        for (int wy = 0; wy < 5; ++wy) {
            const float* rp = &s_mag[row + wy][c0];
            float4 a = *(const float4*)rp;
            float4 bq = *(const float4*)(rp + 4);
            float v[8] = {a.x, a.y, a.z, a.w, bq.x, bq.y, bq.z, bq.w};
#pragma unroll
            for (int j = 0; j < 4; ++j)
#pragma unroll
                for (int k = 0; k < 5; ++k)
                    o[j] = fmaf(sT5[wy * 5 + k], v[j + k], o[j]);
        }
        int gy = ty0 + row, gx = tx0 + c0;
        if (edge) {
#pragma unroll
            for (int j = 0; j < 4; ++j) {
                int gxx = gx + j;
                if (gy < 1 || gy > IH - 2 || gxx < 1 || gxx > IW - 2) {
                    float acc = 0.f;
                    for (int vy = 0; vy < 3; ++vy)
                        for (int vx = 0; vx < 3; ++vx) {
                            int ry = gy + vy - 1, rx = gxx + vx - 1;
                            if (ry < 0 || ry >= IH || rx < 0 || rx >= IW) continue;
                            for (int sy = 0; sy < 3; ++sy)
                                for (int sx2 = 0; sx2 < 3; ++sx2)
                                    acc = fmaf(sNM[(vy * 3 + vx) * 9 + sy * 3 + sx2],
                                               s_mag[row + vy + sy][c0 + j + vx + sx2], acc);
                        }
                    o[j] = acc;
                }
            }
        }
        *(float4*)&ob[gy * IW + gx] = make_float4(o[0], o[1], o[2], o[3]);
    }
}

extern "C" void kernel_launch(void* const* d_in, const int* in_sizes, int n_in,
                              void* d_out, int out_size) {
    const float* img   = (const float*)d_in[0];
    const float* gauss = (const float*)d_in[1];
    const float* sx    = (const float*)d_in[2];
    const float* sy    = (const float*)d_in[3];
    const float* dirw  = (const float*)d_in[4];
    const float* nmsw  = (const float*)d_in[5];
    float* out = (float*)d_out;

    prep_weights<<<1, 128>>>(gauss, sx, sy, dirw, nmsw);

    dim3 grid(IW / TX, IH / TY, NB);
    canny_fused<<<grid, 256>>>(img, out);
}